// round 2
// baseline (speedup 1.0000x reference)
#include <cuda_runtime.h>
#include <math.h>

#define N_TOK    16384
#define HID      4096
#define NE       64
#define TM       128          // tokens per CTA
#define KT       32           // K-tile width (floats)
#define KK2      (KT/2)       // 16 float2 pairs per tile
#define NKT      (HID/KT)     // 128 K-tiles
#define NTHREADS 256

// Global accumulators for the aux-loss reductions (no cudaMalloc allowed).
__device__ float g_P[NE];     // sum over tokens of softmax probs, per expert
__device__ float g_cnt[NE];   // tokens_per_expert counts
__device__ float g_z;         // sum of logsumexp^2

// ---------- packed f32x2 helpers (sm_103a FFMA2 path) ----------
__device__ __forceinline__ unsigned long long pk2(float x, float y) {
    unsigned long long r;
    asm("mov.b64 %0, {%1, %2};" : "=l"(r) : "f"(x), "f"(y));
    return r;
}
__device__ __forceinline__ void upk2(unsigned long long v, float &x, float &y) {
    asm("mov.b64 {%0, %1}, %2;" : "=f"(x), "=f"(y) : "l"(v));
}
__device__ __forceinline__ void fma2(unsigned long long &d, unsigned long long a,
                                     unsigned long long b) {
    asm("fma.rn.f32x2 %0, %1, %2, %0;" : "+l"(d) : "l"(a), "l"(b));
}

__global__ void __launch_bounds__(NTHREADS, 1)
router_main(const float* __restrict__ X, const float* __restrict__ Wg,
            float* __restrict__ out)
{
    // Double-buffered k-major tiles stored as packed float2 (8B) words.
    // As: [buf][kk][token^kk]   Ws: [buf][kk][expert^kk]   (XOR swizzle, conflict-free)
    __shared__ unsigned long long As[2][KK2 * TM];   // 2*16*128*8 = 32 KB
    __shared__ unsigned long long Ws[2][KK2 * NE];   // 2*16*64*8  = 16 KB  (total 48 KB)

    const int tid = threadIdx.x;
    const int t0  = blockIdx.x * TM;
    const int c8  = tid & 7;      // float4 column group for loads / expert low bits
    const int rg  = tid >> 3;     // 0..31
    const int tg4 = rg * 4;       // this thread's 4 tokens: tg4..tg4+3
    const int eg  = c8;           // this thread's 8 experts: eg + 8j

    unsigned long long acc[4][8];
#pragma unroll
    for (int i = 0; i < 4; i++)
#pragma unroll
        for (int j = 0; j < 8; j++) acc[i][j] = 0ull;

    const float4* Xv = reinterpret_cast<const float4*>(X) + (size_t)t0 * (HID / 4);
    const float4* Wv = reinterpret_cast<const float4*>(Wg);

    float4 ra[4], rw[2];

    auto LOAD = [&](int kt) {
        const int cc = kt * 8 + c8;     // float4 index in row
#pragma unroll
        for (int i = 0; i < 4; i++)
            ra[i] = Xv[(size_t)(rg + 32 * i) * (HID / 4) + cc];
#pragma unroll
        for (int i = 0; i < 2; i++)
            rw[i] = Wv[(size_t)(rg + 32 * i) * (HID / 4) + cc];
    };

    auto STORE = [&](int b) {
        const int kk0 = c8 * 2;
#pragma unroll
        for (int i = 0; i < 4; i++) {
            const int t = rg + 32 * i;
            As[b][ kk0      * TM + (t ^  kk0     )] = pk2(ra[i].x, ra[i].y);
            As[b][(kk0 + 1) * TM + (t ^ (kk0 + 1))] = pk2(ra[i].z, ra[i].w);
        }
#pragma unroll
        for (int i = 0; i < 2; i++) {
            const int e = rg + 32 * i;
            Ws[b][ kk0      * NE + (e ^  kk0     )] = pk2(rw[i].x, rw[i].y);
            Ws[b][(kk0 + 1) * NE + (e ^ (kk0 + 1))] = pk2(rw[i].z, rw[i].w);
        }
    };

    auto COMPUTE = [&](int b) {
#pragma unroll
        for (int kk = 0; kk < KK2; kk++) {
            unsigned long long a2[4], b2[8];
#pragma unroll
            for (int i = 0; i < 4; i++)
                a2[i] = As[b][kk * TM + ((tg4 + i) ^ kk)];
#pragma unroll
            for (int j = 0; j < 8; j++)
                b2[j] = Ws[b][kk * NE + ((eg + 8 * j) ^ kk)];
#pragma unroll
            for (int i = 0; i < 4; i++)
#pragma unroll
                for (int j = 0; j < 8; j++)
                    fma2(acc[i][j], a2[i], b2[j]);
        }
    };

    // ---- main K loop: LDG(next) -> compute(cur) -> STS(next) -> sync ----
    LOAD(0);
    STORE(0);
    __syncthreads();
    int cur = 0;
    for (int kt = 0; kt < NKT; kt++) {
        const bool more = (kt + 1 < NKT);
        if (more) LOAD(kt + 1);
        COMPUTE(cur);
        if (more) STORE(cur ^ 1);
        __syncthreads();
        cur ^= 1;
    }

    // ---- epilogue: fold f32x2 accumulators, write logits to smem ----
    float* Ls    = reinterpret_cast<float*>(As);   // 8192 floats = 128 x 64 (swizzled)
    float* shp   = reinterpret_cast<float*>(Ws);   // [0..63]  prob sums
    float* shcnt = shp + NE;                       // [64..127] counts
    float* shz   = shp + 2 * NE;                   // [128]     lse^2 sum

#pragma unroll
    for (int i = 0; i < 4; i++) {
        const int t = tg4 + i;
#pragma unroll
        for (int j = 0; j < 8; j++) {
            const int e = eg + 8 * j;
            float x, y;
            upk2(acc[i][j], x, y);
            Ls[t * NE + (e ^ (t & 63))] = x + y;
        }
    }
    if (tid < NE) { shp[tid] = 0.f; shcnt[tid] = 0.f; }
    if (tid == 0) shz[0] = 0.f;
    __syncthreads();

    if (tid < TM) {
        const int t  = tid;
        const int sx = t & 63;
        // top-2 over logits (same order as probs); strict > keeps lowest index on ties
        float l1 = -1e30f, l2 = -1e30f;
        int   i1 = 0,      i2 = 0;
        for (int e = 0; e < NE; e++) {
            const float v = Ls[t * NE + (e ^ sx)];
            if (v > l1)      { l2 = l1; i2 = i1; l1 = v; i1 = e; }
            else if (v > l2) { l2 = v;  i2 = e; }
        }
        // softmax (max = l1), store unnormalized probs back to smem
        float s = 0.f;
        for (int e = 0; e < NE; e++) {
            const int idx = t * NE + (e ^ sx);
            const float p = expf(Ls[idx] - l1);
            s += p;
            Ls[idx] = p;
        }
        const float inv_s = 1.f / s;
        const float lse   = l1 + logf(s);

        const float p2   = expf(l2 - l1);   // p1 = 1
        const float wsum = 1.f + p2;
        const int   gt   = t0 + t;
        out[2 * gt]              = 1.f / wsum;
        out[2 * gt + 1]          = p2 / wsum;
        out[2 * N_TOK + 2 * gt]     = (float)i1;
        out[2 * N_TOK + 2 * gt + 1] = (float)i2;

        atomicAdd(&shcnt[i1], 1.f);
        atomicAdd(&shcnt[i2], 1.f);
        atomicAdd(shz, lse * lse);
        // staggered per-expert prob accumulation (spread smem banks)
        for (int q = 0; q < NE; q++) {
            const int e = (q + t) & 63;
            atomicAdd(&shp[e], Ls[t * NE + (e ^ sx)] * inv_s);
        }
    }
    __syncthreads();

    if (tid < NE) {
        atomicAdd(&g_P[tid],   shp[tid]);
        atomicAdd(&g_cnt[tid], shcnt[tid]);
    }
    if (tid == 0) atomicAdd(&g_z, shz[0]);
}

__global__ void router_zero()
{
    const int t = threadIdx.x;
    if (t < NE) { g_P[t] = 0.f; g_cnt[t] = 0.f; }
    if (t == 0) g_z = 0.f;
}

__global__ void router_finalize(float* __restrict__ out)
{
    __shared__ float red[NE];
    const int e = threadIdx.x;
    const float f = g_cnt[e] * (1.f / (N_TOK * 2.f));
    const float P = g_P[e]   * (1.f / N_TOK);
    red[e] = f * P;
    __syncthreads();
    if (e < 32) red[e] += red[e + 32];
    __syncthreads();
    if (e < 32) {
        float v = red[e];
#pragma unroll
        for (int off = 16; off > 0; off >>= 1)
            v += __shfl_down_sync(0xffffffffu, v, off);
        if (e == 0) {
            const float lb = (float)NE * v;
            const float z  = g_z * (1.f / N_TOK);
            out[4 * N_TOK] = 0.001f * lb + 0.001f * z;
        }
    }
}

extern "C" void kernel_launch(void* const* d_in, const int* in_sizes, int n_in,
                              void* d_out, int out_size)
{
    (void)in_sizes; (void)n_in; (void)out_size;
    const float* X  = (const float*)d_in[0];
    const float* Wg = (const float*)d_in[1];
    float* out = (float*)d_out;

    router_zero<<<1, 64>>>();
    router_main<<<N_TOK / TM, NTHREADS>>>(X, Wg, out);
    router_finalize<<<1, 64>>>(out);
}

// round 4
// speedup vs baseline: 2.1532x; 2.1532x over previous
#include <cuda_runtime.h>
#include <cuda_fp16.h>
#include <math.h>
#include <stdint.h>

#define N_TOK    16384
#define HID      4096
#define NE       64
#define TM       128
#define KT       64                  // K-tile (fp32 elements)
#define NKT      (HID/KT)            // 64
#define NTHREADS 256

// smem layout (bytes). Row stride = 72 halves = 144 B (pad => conflict-free frags)
#define SM_RED    0                  // 64 P + 64 cnt + 1 z floats (< 1024)
#define BUF0      1024
#define OFF_AHI   0
#define OFF_ALO   18432              // 128*144
#define OFF_BHI   36864
#define OFF_BLO   46080              // +64*144
#define BUF_BYTES 55296
#define SMEM_TOTAL (BUF0 + 2*BUF_BYTES)   // 111616
#define LS_OFF    BUF0               // epilogue logits 128 x 65 fp32 (reuses buf0)

__device__ float g_P[NE];
__device__ float g_cnt[NE];
__device__ float g_z;

__device__ __forceinline__ void mma16816(float* c, const uint32_t* a, const uint32_t* b) {
    asm volatile(
        "mma.sync.aligned.m16n8k16.row.col.f32.f16.f16.f32 "
        "{%0,%1,%2,%3}, {%4,%5,%6,%7}, {%8,%9}, {%0,%1,%2,%3};"
        : "+f"(c[0]), "+f"(c[1]), "+f"(c[2]), "+f"(c[3])
        : "r"(a[0]), "r"(a[1]), "r"(a[2]), "r"(a[3]), "r"(b[0]), "r"(b[1]));
}

__device__ __forceinline__ void split4(float4 v, uint2& hi, uint2& lo) {
    __half2 h01 = __floats2half2_rn(v.x, v.y);
    __half2 h23 = __floats2half2_rn(v.z, v.w);
    float2 f01 = __half22float2(h01);
    float2 f23 = __half22float2(h23);
    __half2 l01 = __floats2half2_rn(v.x - f01.x, v.y - f01.y);
    __half2 l23 = __floats2half2_rn(v.z - f23.x, v.w - f23.y);
    hi.x = *reinterpret_cast<uint32_t*>(&h01);
    hi.y = *reinterpret_cast<uint32_t*>(&h23);
    lo.x = *reinterpret_cast<uint32_t*>(&l01);
    lo.y = *reinterpret_cast<uint32_t*>(&l23);
}

__global__ void __launch_bounds__(NTHREADS, 1)
router_main(const float* __restrict__ X, const float* __restrict__ Wg,
            float* __restrict__ out)
{
    extern __shared__ char smem[];
    const int tid  = threadIdx.x;
    const int lane = tid & 31;
    const int wid  = tid >> 5;
    const int t0   = blockIdx.x * TM;
    const int mg   = (wid & 3) * 32;     // warp token base (32 tokens)
    const int ng   = (wid >> 2) * 32;    // warp expert base (32 experts)

    float* shp   = (float*)(smem + SM_RED);
    float* shcnt = shp + NE;
    float* shz   = shp + 2 * NE;
    if (tid < NE) { shp[tid] = 0.f; shcnt[tid] = 0.f; }
    if (tid == 0) shz[0] = 0.f;

    const float4* Xv = reinterpret_cast<const float4*>(X);
    const float4* Wv = reinterpret_cast<const float4*>(Wg);

    // staging element mapping: A 8 float4/thread (128 rows x 16 f4), B 4 f4/thread
    int arow[8], ac4[8], brow[4], bc4[4];
#pragma unroll
    for (int i = 0; i < 8; i++) { int idx = tid + 256 * i; arow[i] = idx >> 4; ac4[i] = idx & 15; }
#pragma unroll
    for (int i = 0; i < 4; i++) { int idx = tid + 256 * i; brow[i] = idx >> 4; bc4[i] = idx & 15; }

    float4 stA[8], stB[4];

    auto LOAD = [&](int kt) {
#pragma unroll
        for (int i = 0; i < 8; i++)
            stA[i] = Xv[(size_t)(t0 + arow[i]) * (HID / 4) + kt * 16 + ac4[i]];
#pragma unroll
        for (int i = 0; i < 4; i++)
            stB[i] = Wv[(size_t)brow[i] * (HID / 4) + kt * 16 + bc4[i]];
    };

    auto STS = [&](int buf) {
        char* bp = smem + BUF0 + buf * BUF_BYTES;
        uint2* pAH = (uint2*)(bp + OFF_AHI);
        uint2* pAL = (uint2*)(bp + OFF_ALO);
        uint2* pBH = (uint2*)(bp + OFF_BHI);
        uint2* pBL = (uint2*)(bp + OFF_BLO);
#pragma unroll
        for (int i = 0; i < 8; i++) {
            uint2 h, l; split4(stA[i], h, l);
            int o = arow[i] * 18 + ac4[i];
            pAH[o] = h; pAL[o] = l;
        }
#pragma unroll
        for (int i = 0; i < 4; i++) {
            uint2 h, l; split4(stB[i], h, l);
            int o = brow[i] * 18 + bc4[i];
            pBH[o] = h; pBL[o] = l;
        }
    };

    float acc[2][4][4];
#pragma unroll
    for (int mt = 0; mt < 2; mt++)
#pragma unroll
        for (int nt = 0; nt < 4; nt++)
#pragma unroll
            for (int k = 0; k < 4; k++) acc[mt][nt][k] = 0.f;

    const int aoff0 = (mg + (lane >> 2)) * 36 + (lane & 3);   // u32 units, row stride 36
    const int boff0 = (ng + (lane >> 2)) * 36 + (lane & 3);

    auto COMPUTE = [&](int buf) {
        const char* bp = smem + BUF0 + buf * BUF_BYTES;
        const uint32_t* AH = (const uint32_t*)(bp + OFF_AHI);
        const uint32_t* AL = (const uint32_t*)(bp + OFF_ALO);
        const uint32_t* BH = (const uint32_t*)(bp + OFF_BHI);
        const uint32_t* BL = (const uint32_t*)(bp + OFF_BLO);
#pragma unroll
        for (int kc = 0; kc < 4; kc++) {
            const int kb = kc * 8;
            uint32_t ah[2][4], al[2][4], bh[4][2], bl[4][2];
#pragma unroll
            for (int mt = 0; mt < 2; mt++) {
                const int ba = aoff0 + mt * 576 + kb;        // 16 rows * 36
                ah[mt][0] = AH[ba];       ah[mt][1] = AH[ba + 288];
                ah[mt][2] = AH[ba + 4];   ah[mt][3] = AH[ba + 292];
                al[mt][0] = AL[ba];       al[mt][1] = AL[ba + 288];
                al[mt][2] = AL[ba + 4];   al[mt][3] = AL[ba + 292];
            }
#pragma unroll
            for (int nt = 0; nt < 4; nt++) {
                const int bb = boff0 + nt * 288 + kb;        // 8 rows * 36
                bh[nt][0] = BH[bb];  bh[nt][1] = BH[bb + 4];
                bl[nt][0] = BL[bb];  bl[nt][1] = BL[bb + 4];
            }
#pragma unroll
            for (int mt = 0; mt < 2; mt++)
#pragma unroll
                for (int nt = 0; nt < 4; nt++) {
                    mma16816(acc[mt][nt], ah[mt], bh[nt]);
                    mma16816(acc[mt][nt], ah[mt], bl[nt]);
                    mma16816(acc[mt][nt], al[mt], bh[nt]);
                }
        }
    };

    // ---- pipeline: one syncthreads per K-tile ----
    LOAD(0);
    STS(0);
    __syncthreads();
    for (int kt = 0; kt < NKT; kt++) {
        const int buf = kt & 1;
        if (kt + 1 < NKT) LOAD(kt + 1);
        COMPUTE(buf);
        if (kt + 1 < NKT) STS(buf ^ 1);
        __syncthreads();
    }

    // ---- scatter accumulators to padded logits buffer ----
    float* Ls = (float*)(smem + LS_OFF);                // [128][65]
    {
        const int r = lane >> 2;
        const int c = 2 * (lane & 3);
#pragma unroll
        for (int mt = 0; mt < 2; mt++)
#pragma unroll
            for (int nt = 0; nt < 4; nt++) {
                const int row = mg + mt * 16 + r;
                const int col = ng + nt * 8 + c;
                Ls[row * 65 + col]           = acc[mt][nt][0];
                Ls[row * 65 + col + 1]       = acc[mt][nt][1];
                Ls[(row + 8) * 65 + col]     = acc[mt][nt][2];
                Ls[(row + 8) * 65 + col + 1] = acc[mt][nt][3];
            }
    }
    __syncthreads();

    // ---- per-token epilogue (tokens 0..127 on threads 0..127) ----
    if (tid < TM) {
        const float* row = Ls + tid * 65;
        float l1 = -1e30f, l2 = -1e30f; int i1 = 0, i2 = 0;
#pragma unroll
        for (int e = 0; e < NE; e++) {
            const float v = row[e];
            if (v > l1)      { l2 = l1; i2 = i1; l1 = v; i1 = e; }
            else if (v > l2) { l2 = v; i2 = e; }
        }
        float s = 0.f;
        float p[NE];
#pragma unroll
        for (int e = 0; e < NE; e++) { p[e] = expf(row[e] - l1); s += p[e]; }
        const float inv_s = 1.f / s;
        const float lse   = l1 + logf(s);

        const float p2   = expf(l2 - l1);
        const float wsum = 1.f + p2;
        const int   gt   = t0 + tid;
        out[2 * gt]                 = 1.f / wsum;
        out[2 * gt + 1]             = p2 / wsum;
        out[2 * N_TOK + 2 * gt]     = (float)i1;
        out[2 * N_TOK + 2 * gt + 1] = (float)i2;

        // per-expert prob sums: warp shfl-reduce then one atomic per expert per warp
#pragma unroll
        for (int e = 0; e < NE; e++) {
            float v = p[e] * inv_s;
#pragma unroll
            for (int o = 16; o > 0; o >>= 1) v += __shfl_xor_sync(0xffffffffu, v, o);
            if (lane == 0) atomicAdd(&shp[e], v);
        }
        atomicAdd(&shcnt[i1], 1.f);
        atomicAdd(&shcnt[i2], 1.f);
        float zv = lse * lse;
#pragma unroll
        for (int o = 16; o > 0; o >>= 1) zv += __shfl_xor_sync(0xffffffffu, zv, o);
        if (lane == 0) atomicAdd(shz, zv);
    }
    __syncthreads();

    if (tid < NE) {
        atomicAdd(&g_P[tid],   shp[tid]);
        atomicAdd(&g_cnt[tid], shcnt[tid]);
    }
    if (tid == 0) atomicAdd(&g_z, shz[0]);
}

__global__ void router_zero()
{
    const int t = threadIdx.x;
    if (t < NE) { g_P[t] = 0.f; g_cnt[t] = 0.f; }
    if (t == 0) g_z = 0.f;
}

__global__ void router_finalize(float* __restrict__ out)
{
    __shared__ float red[NE];
    const int e = threadIdx.x;
    const float f = g_cnt[e] * (1.f / (N_TOK * 2.f));
    const float P = g_P[e]   * (1.f / N_TOK);
    red[e] = f * P;
    __syncthreads();
    if (e < 32) red[e] += red[e + 32];
    __syncthreads();
    if (e < 32) {
        float v = red[e];
#pragma unroll
        for (int off = 16; off > 0; off >>= 1)
            v += __shfl_down_sync(0xffffffffu, v, off);
        if (e == 0) {
            const float lb = (float)NE * v;
            const float z  = g_z * (1.f / N_TOK);
            out[4 * N_TOK] = 0.001f * lb + 0.001f * z;
        }
    }
}

extern "C" void kernel_launch(void* const* d_in, const int* in_sizes, int n_in,
                              void* d_out, int out_size)
{
    (void)in_sizes; (void)n_in; (void)out_size;
    const float* X  = (const float*)d_in[0];
    const float* Wg = (const float*)d_in[1];
    float* out = (float*)d_out;

    cudaFuncSetAttribute(router_main, cudaFuncAttributeMaxDynamicSharedMemorySize, SMEM_TOTAL);

    router_zero<<<1, 64>>>();
    router_main<<<N_TOK / TM, NTHREADS, SMEM_TOTAL>>>(X, Wg, out);
    router_finalize<<<1, 64>>>(out);
}